// round 7
// baseline (speedup 1.0000x reference)
#include <cuda_runtime.h>

#define HH 224
#define WW 224
#define STEPS 32
#define NWARP 8
#define RPS 5               // vertex rows per strip: 45 strips * 5 = 225 rows
#define NSTRIPS 45
#define BLOCKS_PER_IMG 45   // 45 strips * 8 col-groups / 8 warps-per-block
#define MAX_IMGS 64

// zero-initialized device scratch; finalize_kernel restores it to zero each run
__device__ int g_scratch[MAX_IMGS * STEPS];

// bucket index: smallest k with value <= t_k, t_k = -2 + 4k/31; 63 = "never counts"
__device__ __forceinline__ int bucketf(float v) {
    float r = fmaf(v, 7.75f, 15.5f);      // (v + 2) * 31/4
    int k = __float2int_ru(r);            // inf -> INT_MAX
    k = max(k, 0);
    k = min(k, 63);
    return k;
}

__global__ __launch_bounds__(256) void ecc_kernel(const float* __restrict__ x) {
    __shared__ int hist[NWARP * 32];
    const int tid = threadIdx.x;
    hist[tid] = 0;
    __syncthreads();

    const int img  = blockIdx.y;
    const float* p = x + (size_t)img * (HH * WW);
    const int warp = tid >> 5;
    const int lane = tid & 31;
    const int wl   = blockIdx.x * NWARP + warp;  // 0..359
    const int cg   = wl & 7;                     // column group 0..7
    const int strip = wl >> 3;                   // 0..44
    const int j    = cg * 32 + lane;             // vertex column
    const int i0   = strip * RPS;
    const int rbase = i0 - 1;

    int* h = hist + warp * 32;

    const bool rc = (strip == 0) | (strip == NSTRIPS - 1);  // rows -1 or 224 present

    int b[RPS + 1];
    if (!rc) {
        if (cg < 7) {
            // fully interior: unguarded coalesced loads
#pragma unroll
            for (int r = 0; r <= RPS; r++)
                b[r] = bucketf(__ldg(p + (rbase + r) * WW + j));
        } else {
            // column guard only
#pragma unroll
            for (int r = 0; r <= RPS; r++)
                b[r] = (j < WW) ? bucketf(__ldg(p + (rbase + r) * WW + j)) : 63;
        }
    } else {
        // row + column guards
#pragma unroll
        for (int r = 0; r <= RPS; r++) {
            const int rr = rbase + r;
            b[r] = ((unsigned)rr < HH && j < WW) ? bucketf(__ldg(p + rr * WW + j)) : 63;
        }
    }

    // left-neighbor buckets via shuffle; lane 0 loads column j-1 itself
    int bl[RPS + 1];
#pragma unroll
    for (int r = 0; r <= RPS; r++)
        bl[r] = __shfl_up_sync(0xffffffffu, b[r], 1);
    if (lane == 0) {
        const int jm = j - 1;
        const bool cok = (unsigned)jm < WW;
#pragma unroll
        for (int r = 0; r <= RPS; r++) {
            const int rr = rbase + r;
            const bool ok = cok && (!rc || (unsigned)rr < HH);
            bl[r] = ok ? bucketf(__ldg(p + rr * WW + jm)) : 63;
        }
    }

#pragma unroll
    for (int r = 1; r <= RPS; r++) {
        const int b_up  = b[r - 1];
        const int b_ul  = bl[r - 1];
        const int b_cur = b[r];
        const int b_l   = bl[r];

        const int eh  = min(b_up, b_cur);   // horizontal edge
        const int ev  = min(b_l,  b_cur);   // vertical edge
        const int emn = min(eh, ev);
        const int emx = max(eh, ev);
        const int kv  = min(emn, b_ul);     // vertex (kv <= emn)
        const int kf  = b_cur;              // face   (emx <= kf)

        // four independent single-instruction predicated atomics
        if (kv < min(emn, 32))            atomicAdd(&h[kv],  1);
        if (kv < emn && emn < 32)         atomicAdd(&h[emn], -1);
        if (emx < min(kf, 32))            atomicAdd(&h[emx], -1);
        if (emx < kf && kf < 32)          atomicAdd(&h[kf],  1);
    }

    __syncthreads();
    // reduce warp replicas; accumulate raw deltas into global scratch (int)
    if (tid < 32) {
        int v = 0;
#pragma unroll
        for (int w = 0; w < NWARP; w++) v += hist[w * 32 + tid];
        atomicAdd(&g_scratch[img * 32 + tid], v);
    }
}

// one block; warp w handles image w: prefix-scan deltas -> ECC, write out, re-zero scratch
__global__ void finalize_kernel(float* __restrict__ out, int n) {
    const int t = threadIdx.x;
    const int lane = t & 31;
    int v = (t < n) ? g_scratch[t] : 0;
#pragma unroll
    for (int d = 1; d < 32; d <<= 1) {
        int u = __shfl_up_sync(0xffffffffu, v, d);
        if (lane >= d) v += u;
    }
    if (t < n) {
        out[t] = (float)v;
        g_scratch[t] = 0;   // restore invariant for next graph replay
    }
}

extern "C" void kernel_launch(void* const* d_in, const int* in_sizes, int n_in,
                              void* d_out, int out_size) {
    const float* x = (const float*)d_in[0];
    float* out = (float*)d_out;
    const int imgs = in_sizes[0] / (HH * WW);   // 8*3 = 24

    dim3 grid(BLOCKS_PER_IMG, imgs);
    ecc_kernel<<<grid, 256>>>(x);
    finalize_kernel<<<1, ((imgs * 32 + 31) / 32) * 32>>>(out, imgs * 32);
}

// round 8
// speedup vs baseline: 1.2514x; 1.2514x over previous
#include <cuda_runtime.h>

#define HH 224
#define WW 224
#define STEPS 32
#define NWARP 8
#define RPS 5               // vertex rows per strip: 45 strips * 5 = 225 rows
#define NSTRIPS 45
#define BLOCKS_PER_IMG 45
#define MAX_IMGS 64

// zero-initialized device scratch; finalize path restores zeros every run
__device__ int g_scratch[MAX_IMGS * STEPS];
__device__ unsigned g_count;

// bucket index: smallest k with value <= t_k, t_k = -2 + 4k/31; 63 = "never counts"
__device__ __forceinline__ int bucketf(float v) {
    float r = fmaf(v, 7.75f, 15.5f);      // (v + 2) * 31/4
    int k = __float2int_ru(r);            // inf -> INT_MAX
    k = max(k, 0);
    k = min(k, 63);
    return k;
}

__global__ __launch_bounds__(256) void ecc_kernel(const float* __restrict__ x,
                                                  float* __restrict__ out) {
    __shared__ int hist[NWARP * 32];
    __shared__ bool is_last;
    const int tid = threadIdx.x;
    hist[tid] = 0;
    if (tid == 0) is_last = false;
    __syncthreads();

    const int img  = blockIdx.y;
    const float* p = x + (size_t)img * (HH * WW);
    const int warp = tid >> 5;
    const int lane = tid & 31;
    const int wl   = blockIdx.x * NWARP + warp;  // 0..359
    const int cg   = wl & 7;                     // column group 0..7
    const int strip = wl >> 3;                   // 0..44
    const int j    = cg * 32 + lane;             // vertex column
    const int i0   = strip * RPS;
    const int rbase = i0 - 1;

    int* h = hist + warp * 32;

    const bool rc = (strip == 0) | (strip == NSTRIPS - 1);  // rows -1 or 224 present

    int b[RPS + 1];
    if (!rc) {
        if (cg < 7) {
#pragma unroll
            for (int r = 0; r <= RPS; r++)
                b[r] = bucketf(__ldg(p + (rbase + r) * WW + j));
        } else {
#pragma unroll
            for (int r = 0; r <= RPS; r++)
                b[r] = (j < WW) ? bucketf(__ldg(p + (rbase + r) * WW + j)) : 63;
        }
    } else {
#pragma unroll
        for (int r = 0; r <= RPS; r++) {
            const int rr = rbase + r;
            b[r] = ((unsigned)rr < HH && j < WW) ? bucketf(__ldg(p + rr * WW + j)) : 63;
        }
    }

    // left-neighbor buckets via shuffle; lane 0 loads column j-1 itself
    int bl[RPS + 1];
#pragma unroll
    for (int r = 0; r <= RPS; r++)
        bl[r] = __shfl_up_sync(0xffffffffu, b[r], 1);
    if (lane == 0) {
        const int jm = j - 1;
        const bool cok = (unsigned)jm < WW;
#pragma unroll
        for (int r = 0; r <= RPS; r++) {
            const int rr = rbase + r;
            const bool ok = cok && (!rc || (unsigned)rr < HH);
            bl[r] = ok ? bucketf(__ldg(p + rr * WW + jm)) : 63;
        }
    }

#pragma unroll
    for (int r = 1; r <= RPS; r++) {
        const int b_up  = b[r - 1];
        const int b_ul  = bl[r - 1];
        const int b_cur = b[r];
        const int b_l   = bl[r];

        const int eh  = min(b_up, b_cur);   // horizontal edge
        const int ev  = min(b_l,  b_cur);   // vertical edge
        const int emn = min(eh, ev);
        const int emx = max(eh, ev);
        const int kv  = min(emn, b_ul);     // vertex (kv <= emn)
        const int kf  = b_cur;              // face   (emx <= kf)

        if (kv < min(emn, 32))            atomicAdd(&h[kv],  1);
        if (kv < emn && emn < 32)         atomicAdd(&h[emn], -1);
        if (emx < min(kf, 32))            atomicAdd(&h[emx], -1);
        if (emx < kf && kf < 32)          atomicAdd(&h[kf],  1);
    }

    __syncthreads();
    // reduce warp replicas; accumulate raw deltas into global scratch (int)
    if (tid < 32) {
        int v = 0;
#pragma unroll
        for (int w = 0; w < NWARP; w++) v += hist[w * 32 + tid];
        atomicAdd(&g_scratch[img * 32 + tid], v);
        __threadfence();                    // make this block's adds globally visible
    }
    __syncthreads();

    const unsigned nblocks = gridDim.x * gridDim.y;
    if (tid == 0) {
        unsigned old = atomicAdd(&g_count, 1u);
        is_last = (old == nblocks - 1u);
    }
    __syncthreads();

    if (is_last) {
        const int nimg = gridDim.y;
        // warp w handles images w, w+8, ... : scan deltas -> ECC, write out, re-zero
        for (int im = warp; im < nimg; im += NWARP) {
            const int idx = im * 32 + lane;
            int v = atomicExch(&g_scratch[idx], 0);   // read + restore zero invariant
#pragma unroll
            for (int d = 1; d < 32; d <<= 1) {
                int u = __shfl_up_sync(0xffffffffu, v, d);
                if (lane >= d) v += u;
            }
            out[idx] = (float)v;
        }
        if (tid == 0) atomicExch(&g_count, 0u);       // reset for next replay
    }
}

extern "C" void kernel_launch(void* const* d_in, const int* in_sizes, int n_in,
                              void* d_out, int out_size) {
    const float* x = (const float*)d_in[0];
    float* out = (float*)d_out;
    const int imgs = in_sizes[0] / (HH * WW);   // 8*3 = 24

    dim3 grid(BLOCKS_PER_IMG, imgs);
    ecc_kernel<<<grid, 256>>>(x, out);
}

// round 10
// speedup vs baseline: 1.4652x; 1.1709x over previous
#include <cuda_runtime.h>

#define HH 224
#define WW 224
#define STEPS 32
#define NWARP 8
#define RPS 5               // vertex rows per strip: 45 strips * 5 = 225 rows
#define NSTRIPS 45
#define BLOCKS_PER_IMG 45
#define SENT 63             // sentinel bucket (>=32 -> never counted)

// bucket index: smallest k with value <= t_k, t_k = -2 + 4k/31
__device__ __forceinline__ int bucketf(float v) {
    float r = fmaf(v, 7.75f, 15.5f);      // (v + 2) * 31/4
    int k = __float2int_ru(r);
    return max(k, 0);                     // upper clamp unnecessary: >=32 is inert
}

__global__ __launch_bounds__(256) void ecc_kernel(const float* __restrict__ x,
                                                  float* __restrict__ out) {
    __shared__ int hist[NWARP * 32];
    const int tid = threadIdx.x;
    hist[tid] = 0;
    __syncthreads();

    const int img  = blockIdx.y;
    const float* p = x + (size_t)img * (HH * WW);
    const int warp = tid >> 5;
    const int lane = tid & 31;
    const int cg   = warp;                 // column group == warp id (block-uniform strip)
    const int strip = blockIdx.x;          // 0..44
    const int j    = cg * 32 + lane;       // vertex column
    const int rbase = strip * RPS - 1;

    int* h = hist + warp * 32;

    const bool rc = (strip == 0) | (strip == NSTRIPS - 1);

    // load pixel buckets for columns j and j-1, rows rbase..rbase+RPS (MLP=12, no shuffles)
    int b[RPS + 1], bl[RPS + 1];
    if (!rc && cg >= 1 && cg <= 6) {
        // fully interior: unguarded
        const float* q = p + rbase * WW + j;
#pragma unroll
        for (int r = 0; r <= RPS; r++) {
            b[r]  = bucketf(__ldg(q + r * WW));
            bl[r] = bucketf(__ldg(q + r * WW - 1));
        }
    } else if (!rc) {
        // row-interior, column-edge warp (cg==0 or cg==7)
        const bool jok  = (unsigned)j < WW;
        const bool jmok = (unsigned)(j - 1) < WW;
        const float* q = p + rbase * WW + j;
#pragma unroll
        for (int r = 0; r <= RPS; r++) {
            b[r]  = jok  ? bucketf(__ldg(q + r * WW))     : SENT;
            bl[r] = jmok ? bucketf(__ldg(q + r * WW - 1)) : SENT;
        }
    } else {
        // boundary strip: full guards
        const bool jok  = (unsigned)j < WW;
        const bool jmok = (unsigned)(j - 1) < WW;
#pragma unroll
        for (int r = 0; r <= RPS; r++) {
            const int rr = rbase + r;
            const bool rok = (unsigned)rr < HH;
            b[r]  = (rok && jok)  ? bucketf(__ldg(p + rr * WW + j))     : SENT;
            bl[r] = (rok && jmok) ? bucketf(__ldg(p + rr * WW + j - 1)) : SENT;
        }
    }

#pragma unroll
    for (int r = 1; r <= RPS; r++) {
        const int b_up  = b[r - 1];    // (i-1, j)
        const int b_ul  = bl[r - 1];   // (i-1, j-1)
        const int b_cur = b[r];        // (i,   j)
        const int b_l   = bl[r];       // (i,   j-1)

        const int eh  = min(b_up, b_cur);   // horizontal edge
        const int ev  = min(b_l,  b_cur);   // vertical edge
        const int emn = min(eh, ev);
        const int emx = max(eh, ev);
        const int kv  = min(emn, b_ul);     // vertex (kv <= emn)
        const int kf  = b_cur;              // face   (emx <= kf)

        // delta histogram with cancellation; predicated single-instruction atomics
        if (kv < min(emn, 32))            atomicAdd(&h[kv],  1);
        if (kv < emn && emn < 32)         atomicAdd(&h[emn], -1);
        if (emx < min(kf, 32))            atomicAdd(&h[emx], -1);
        if (emx < kf && kf < 32)          atomicAdd(&h[kf],  1);
    }

    __syncthreads();
    // reduce warp replicas, prefix-scan delta -> cumulative ECC, flush to gmem
    if (tid < 32) {
        int v = 0;
#pragma unroll
        for (int w = 0; w < NWARP; w++) v += hist[w * 32 + tid];
#pragma unroll
        for (int d = 1; d < 32; d <<= 1) {
            int n = __shfl_up_sync(0xffffffffu, v, d);
            if (tid >= d) v += n;
        }
        atomicAdd(out + img * 32 + tid, (float)v);
    }
}

extern "C" void kernel_launch(void* const* d_in, const int* in_sizes, int n_in,
                              void* d_out, int out_size) {
    const float* x = (const float*)d_in[0];
    float* out = (float*)d_out;
    const int imgs = in_sizes[0] / (HH * WW);   // 8*3 = 24

    cudaMemsetAsync(out, 0, (size_t)out_size * sizeof(float), 0);
    dim3 grid(BLOCKS_PER_IMG, imgs);
    ecc_kernel<<<grid, 256>>>(x, out);
}